// round 3
// baseline (speedup 1.0000x reference)
#include <cuda_runtime.h>
#include <math.h>
#include <stdint.h>

// ---------------------------------------------------------------------------
// InternLM2-7B decode-step: qkv GEMM + RoPE + paged KV fill + flash-decode
// attention + output GEMM.  All fp32.  HBM-bound (~1.24 GB/call).
// ---------------------------------------------------------------------------

#define B_       32
#define DMODEL   4096
#define H_       32
#define KVH      8
#define HD_      128
#define GQ       4            // H_/KVH
#define NBLK_    64           // blocks per sequence
#define QKV_N    6144         // (H + 2*KV) * HD
#define SPLITS   8            // split-K for GEMMs
#define KSPLIT   512          // DMODEL / SPLITS
#define ATT_SPLITS 8
#define S2       32           // ATT_SPLITS * 4 warps
#define SCALE_   0.08838834764831843f   // 1/sqrt(128)

// ------------------------- scratch (static, no allocs) ----------------------
__device__ float g_part[SPLITS * B_ * QKV_N];            // gemm partials (reused)
__device__ float g_q   [B_ * H_ * HD_];                  // rope'd Q
__device__ float g_attn[B_ * H_ * HD_];                  // attention output
__device__ float g_acc [B_ * KVH * S2 * GQ * HD_];       // split partial accum
__device__ float g_m   [B_ * KVH * S2];                  // split running max
__device__ float g_l   [B_ * KVH * S2 * GQ];             // split running sum

// ---------------------------------------------------------------------------
// GEMM partial: P[split][32][N] = A[32, k0:k0+KSPLIT] @ W[k0:k0+KSPLIT, :N]
// A row-stride is DMODEL for both uses.  A==nullptr means "use g_attn".
// Inner loop: smem broadcast LDS.128 + packed fma.rn.f32x2 (FFMA2).
// ---------------------------------------------------------------------------
__global__ void gemm_partial_k(const float* __restrict__ A,
                               const float* __restrict__ W, int N)
{
    __shared__ __align__(16) float sA[128 * 36];   // [c][b] padded (stride 36)
    const float* Abase = (A == nullptr) ? g_attn : A;

    const int col = blockIdx.x * 128 + threadIdx.x;
    const int k0  = blockIdx.y * KSPLIT;

    unsigned long long acc[16];                    // 16 x f32x2 = 32 batch rows
#pragma unroll
    for (int i = 0; i < 16; i++) acc[i] = 0ull;

    for (int kt = k0; kt < k0 + KSPLIT; kt += 128) {
        const float* Ap = Abase + kt + threadIdx.x;
#pragma unroll
        for (int b = 0; b < 32; b++)
            sA[threadIdx.x * 36 + b] = Ap[b * DMODEL];
        __syncthreads();

        const float* Wp = W + (size_t)kt * N + col;
#pragma unroll 4
        for (int c = 0; c < 128; c++) {
            float w = Wp[(size_t)c * N];
            unsigned long long wp;
            asm("mov.b64 %0, {%1,%2};" : "=l"(wp) : "f"(w), "f"(w));
            const uint4* ar = (const uint4*)(sA + c * 36);
#pragma unroll
            for (int i = 0; i < 8; i++) {
                uint4 a4 = ar[i];
                unsigned long long p0, p1;
                asm("mov.b64 %0, {%1,%2};" : "=l"(p0) : "r"(a4.x), "r"(a4.y));
                asm("mov.b64 %0, {%1,%2};" : "=l"(p1) : "r"(a4.z), "r"(a4.w));
                asm("fma.rn.f32x2 %0, %1, %2, %0;" : "+l"(acc[2*i])   : "l"(p0), "l"(wp));
                asm("fma.rn.f32x2 %0, %1, %2, %0;" : "+l"(acc[2*i+1]) : "l"(p1), "l"(wp));
            }
        }
        __syncthreads();
    }

    float* out = g_part + ((size_t)blockIdx.y * 32) * N + col;
#pragma unroll
    for (int i = 0; i < 16; i++) {
        float lo, hi;
        asm("mov.b64 {%0,%1}, %2;" : "=f"(lo), "=f"(hi) : "l"(acc[i]));
        out[(size_t)(2 * i)     * N] = lo;
        out[(size_t)(2 * i + 1) * N] = hi;
    }
}

// ---------------------------------------------------------------------------
// Reduce qkv partials, apply RoPE to q & k, write q to g_q, scatter k/v into
// the paged caches.  grid (48 heads, 32 batch), 128 threads (one per dim).
// ---------------------------------------------------------------------------
__global__ void qkv_finish_k(const int* __restrict__ pos_ids,
                             const int* __restrict__ btab,
                             const int* __restrict__ seqlens,
                             float* __restrict__ kc, float* __restrict__ vc)
{
    const int hh = blockIdx.x;        // 0..31 q heads | 32..39 k | 40..47 v
    const int b  = blockIdx.y;
    const int d  = threadIdx.x;
    const int col = hh * 128 + d;

    float v = 0.f;
#pragma unroll
    for (int s = 0; s < SPLITS; s++)
        v += g_part[(size_t)(s * 32 + b) * QKV_N + col];

    float r = v;
    __shared__ float sv[128];
    if (hh < 40) {                      // q and k get RoPE
        sv[d] = v;
        __syncthreads();
        const int i = d & 63;
        const int pos = pos_ids[b];
        double invf = pow(1.0e6, -(double)(2 * i) / 128.0);
        double ang  = (double)pos * invf;
        double sd, cd;
        sincos(ang, &sd, &cd);
        const float cf = (float)cd, sf = (float)sd;
        const float x1 = sv[i], x2 = sv[i + 64];
        r = (d < 64) ? (x1 * cf - x2 * sf) : (x2 * cf + x1 * sf);
    }

    if (hh < 32) {
        g_q[(size_t)b * 4096 + col] = r;
    } else {
        const int kvh = (hh - 32) & 7;
        const int pos = seqlens[b] - 1;
        const int phys = btab[b * NBLK_ + (pos >> 6)];
        const size_t idx = (((size_t)phys * 64 + (pos & 63)) * 8 + kvh) * 128 + d;
        if (hh < 40) kc[idx] = r; else vc[idx] = r;
    }
}

// ---------------------------------------------------------------------------
// Flash-decode partial: grid (8 splits, 8 kvheads, 32 batch), 4 warps/CTA.
// Warp-per-position, float4 K/V loads, joint-max online softmax over the
// 4 GQA heads, one-iteration-ahead prefetch.
// ---------------------------------------------------------------------------
__global__ void attn_partial_k(const float* __restrict__ kcache,
                               const float* __restrict__ vcache,
                               const int* __restrict__ btab,
                               const int* __restrict__ seqlens)
{
    const int split = blockIdx.x, kvh = blockIdx.y, b = blockIdx.z;
    const int warp  = threadIdx.x >> 5, lane = threadIdx.x & 31;
    const int kvlen = seqlens[b];
    const int* bt = btab + b * NBLK_;

    // q for the 4 grouped heads, 4 dims per lane
    float4 q0, q1, q2, q3;
    {
        const float4* qp = (const float4*)(g_q + (size_t)b * 4096 + kvh * GQ * HD_) + lane;
        q0 = qp[0]; q1 = qp[32]; q2 = qp[64]; q3 = qp[96];
    }

    float m = -1e30f;
    float l0 = 0.f, l1 = 0.f, l2 = 0.f, l3 = 0.f;
    float4 a0 = {0,0,0,0}, a1 = a0, a2 = a0, a3 = a0;

    const int pend = split * 512 + 512;
    int p = split * 512 + warp;

    float4 kk = {0,0,0,0}, vv = {0,0,0,0};
    bool valid = (p < kvlen);
    if (valid) {
        const int phys = bt[p >> 6];
        const size_t base = (((size_t)phys * 64 + (p & 63)) * 8 + kvh) * 128 + lane * 4;
        kk = *(const float4*)(kcache + base);
        vv = *(const float4*)(vcache + base);
    }

    while (valid) {
        const float4 kc4 = kk, vc4 = vv;
        const int pn = p + 4;
        const bool nvalid = (pn < pend) && (pn < kvlen);
        if (nvalid) {                                     // prefetch next
            const int phys = bt[pn >> 6];
            const size_t nb = (((size_t)phys * 64 + (pn & 63)) * 8 + kvh) * 128 + lane * 4;
            kk = *(const float4*)(kcache + nb);
            vv = *(const float4*)(vcache + nb);
        }

        float d0 = kc4.x*q0.x + kc4.y*q0.y + kc4.z*q0.z + kc4.w*q0.w;
        float d1 = kc4.x*q1.x + kc4.y*q1.y + kc4.z*q1.z + kc4.w*q1.w;
        float d2 = kc4.x*q2.x + kc4.y*q2.y + kc4.z*q2.z + kc4.w*q2.w;
        float d3 = kc4.x*q3.x + kc4.y*q3.y + kc4.z*q3.z + kc4.w*q3.w;
#pragma unroll
        for (int off = 16; off > 0; off >>= 1) {
            d0 += __shfl_xor_sync(0xffffffffu, d0, off);
            d1 += __shfl_xor_sync(0xffffffffu, d1, off);
            d2 += __shfl_xor_sync(0xffffffffu, d2, off);
            d3 += __shfl_xor_sync(0xffffffffu, d3, off);
        }
        d0 *= SCALE_; d1 *= SCALE_; d2 *= SCALE_; d3 *= SCALE_;

        const float nm   = fmaxf(m, fmaxf(fmaxf(d0, d1), fmaxf(d2, d3)));
        const float corr = __expf(m - nm);
        const float e0 = __expf(d0 - nm);
        const float e1 = __expf(d1 - nm);
        const float e2 = __expf(d2 - nm);
        const float e3 = __expf(d3 - nm);
        l0 = l0 * corr + e0;  l1 = l1 * corr + e1;
        l2 = l2 * corr + e2;  l3 = l3 * corr + e3;

        a0.x = fmaf(e0, vc4.x, a0.x * corr); a0.y = fmaf(e0, vc4.y, a0.y * corr);
        a0.z = fmaf(e0, vc4.z, a0.z * corr); a0.w = fmaf(e0, vc4.w, a0.w * corr);
        a1.x = fmaf(e1, vc4.x, a1.x * corr); a1.y = fmaf(e1, vc4.y, a1.y * corr);
        a1.z = fmaf(e1, vc4.z, a1.z * corr); a1.w = fmaf(e1, vc4.w, a1.w * corr);
        a2.x = fmaf(e2, vc4.x, a2.x * corr); a2.y = fmaf(e2, vc4.y, a2.y * corr);
        a2.z = fmaf(e2, vc4.z, a2.z * corr); a2.w = fmaf(e2, vc4.w, a2.w * corr);
        a3.x = fmaf(e3, vc4.x, a3.x * corr); a3.y = fmaf(e3, vc4.y, a3.y * corr);
        a3.z = fmaf(e3, vc4.z, a3.z * corr); a3.w = fmaf(e3, vc4.w, a3.w * corr);

        m = nm;
        p = pn;
        valid = nvalid;
    }

    // store partials (zeros / -1e30 if this warp saw no positions)
    const int s2 = split * 4 + warp;
    const int pk = b * KVH + kvh;
    float4* ap = (float4*)(g_acc + ((size_t)pk * S2 + s2) * (GQ * HD_));
    ap[lane]      = a0;
    ap[32 + lane] = a1;
    ap[64 + lane] = a2;
    ap[96 + lane] = a3;
    if (lane == 0) g_m[pk * S2 + s2] = m;
    if (lane < 4) {
        const float lv = (lane == 0) ? l0 : (lane == 1) ? l1 : (lane == 2) ? l2 : l3;
        g_l[(pk * S2 + s2) * 4 + lane] = lv;
    }
}

// ---------------------------------------------------------------------------
// Combine the 32 split partials per (b, head).  grid (B*H), 128 threads.
// ---------------------------------------------------------------------------
__global__ void attn_combine_k()
{
    const int bh = blockIdx.x;            // 0..1023
    const int b = bh >> 5, h = bh & 31;
    const int kvh = h >> 2, g = h & 3;
    const int pk = b * KVH + kvh;
    const int d = threadIdx.x;

    __shared__ float sm[S2], sl[S2];
    if (d < S2) {
        sm[d] = g_m[pk * S2 + d];
        sl[d] = g_l[(pk * S2 + d) * 4 + g];
    }
    __syncthreads();

    float gm = -1e30f;
#pragma unroll
    for (int s = 0; s < S2; s++) gm = fmaxf(gm, sm[s]);

    float num = 0.f, den = 0.f;
    const float* accp = g_acc + ((size_t)pk * S2) * (GQ * HD_) + g * HD_ + d;
#pragma unroll 4
    for (int s = 0; s < S2; s++) {
        const float w = __expf(sm[s] - gm);
        den += w * sl[s];
        num += w * accp[(size_t)s * (GQ * HD_)];
    }
    g_attn[(size_t)b * 4096 + h * HD_ + d] = num / den;
}

// ---------------------------------------------------------------------------
// Reduce wo partials into d_out.  grid (32 colblocks, 32 batch).
// ---------------------------------------------------------------------------
__global__ void wo_finish_k(float* __restrict__ out)
{
    const int b = blockIdx.y;
    const int col = blockIdx.x * 128 + threadIdx.x;
    float v = 0.f;
#pragma unroll
    for (int s = 0; s < SPLITS; s++)
        v += g_part[(size_t)(s * 32 + b) * DMODEL + col];
    out[(size_t)b * DMODEL + col] = v;
}

// ---------------------------------------------------------------------------
extern "C" void kernel_launch(void* const* d_in, const int* in_sizes, int n_in,
                              void* d_out, int out_size)
{
    const float* hidden  = (const float*)d_in[0];
    const float* wqkv    = (const float*)d_in[1];
    const float* wo      = (const float*)d_in[2];
    float*       kcache  = (float*)d_in[3];   // mutated in place (idempotent)
    float*       vcache  = (float*)d_in[4];
    const int*   pos_ids = (const int*)d_in[5];
    const int*   btab    = (const int*)d_in[6];
    const int*   seqlens = (const int*)d_in[7];
    float*       out     = (float*)d_out;

    // 1) qkv = hidden @ wqkv  (split-K partials)
    gemm_partial_k<<<dim3(QKV_N / 128, SPLITS), 128>>>(hidden, wqkv, QKV_N);
    // 2) reduce + RoPE + KV-cache fill + stage q
    qkv_finish_k<<<dim3(48, 32), 128>>>(pos_ids, btab, seqlens, kcache, vcache);
    // 3) flash-decode split partials over the paged cache
    attn_partial_k<<<dim3(ATT_SPLITS, KVH, B_), 128>>>(kcache, vcache, btab, seqlens);
    // 4) combine splits -> g_attn
    attn_combine_k<<<B_ * H_, 128>>>();
    // 5) out = g_attn @ wo  (split-K partials; A==nullptr selects g_attn)
    gemm_partial_k<<<dim3(DMODEL / 128, SPLITS), 128>>>(nullptr, wo, DMODEL);
    // 6) reduce partials into d_out
    wo_finish_k<<<dim3(32, 32), 128>>>(out);
}